// round 1
// baseline (speedup 1.0000x reference)
#include <cuda_runtime.h>
#include <math.h>

#define DIN   1024
#define DIMM  1024
#define NH    16
#define HD    64
#define SEQ   2048
#define BATCHN 2
#define MTOT  (BATCHN*SEQ)   // 4096

// Scratch (allocation-free rule: __device__ globals)
__device__ float g_q[MTOT*DIMM];
__device__ float g_k[MTOT*DIMM];
__device__ float g_v[MTOT*DIMM];
__device__ float g_ctx[MTOT*DIMM];

__device__ __forceinline__ float fast_exp2(float x) {
    float y;
    asm("ex2.approx.ftz.f32 %0, %1;" : "=f"(y) : "f"(x));
    return y;
}

// ---------------------------------------------------------------------------
// C[4096,1024] = A[4096,1024] @ W[1024,1024]^T   (torch Linear convention)
// 128x128 tile, BK=16, 256 threads, 8x8 accumulators per thread.
// ---------------------------------------------------------------------------
__global__ void __launch_bounds__(256) gemm_awT(const float* __restrict__ A,
                                               const float* __restrict__ W,
                                               float* __restrict__ C)
{
    const int K = 1024;
    const int N = 1024;
    __shared__ float As[16][128];
    __shared__ float Ws[16][128];

    const int tid = threadIdx.x;
    const int m0 = blockIdx.y * 128;
    const int n0 = blockIdx.x * 128;
    const int tx = tid & 15;       // 0..15  (N direction)
    const int ty = tid >> 4;       // 0..15  (M direction)
    const int lr = tid >> 2;       // 0..63  (load row)
    const int lk = (tid & 3) * 4;  // 0,4,8,12 (load k)

    float acc[8][8];
    #pragma unroll
    for (int i = 0; i < 8; i++)
        #pragma unroll
        for (int j = 0; j < 8; j++)
            acc[i][j] = 0.0f;

    for (int k0 = 0; k0 < K; k0 += 16) {
        #pragma unroll
        for (int r = 0; r < 2; r++) {
            int row = lr + r * 64;
            float4 av = *(const float4*)&A[(size_t)(m0 + row) * K + k0 + lk];
            As[lk + 0][row] = av.x;
            As[lk + 1][row] = av.y;
            As[lk + 2][row] = av.z;
            As[lk + 3][row] = av.w;
            float4 wv = *(const float4*)&W[(size_t)(n0 + row) * K + k0 + lk];
            Ws[lk + 0][row] = wv.x;
            Ws[lk + 1][row] = wv.y;
            Ws[lk + 2][row] = wv.z;
            Ws[lk + 3][row] = wv.w;
        }
        __syncthreads();

        #pragma unroll
        for (int kk = 0; kk < 16; kk++) {
            float a[8], bb[8];
            #pragma unroll
            for (int i = 0; i < 8; i++) a[i]  = As[kk][ty * 8 + i];
            #pragma unroll
            for (int j = 0; j < 8; j++) bb[j] = Ws[kk][tx * 8 + j];
            #pragma unroll
            for (int i = 0; i < 8; i++)
                #pragma unroll
                for (int j = 0; j < 8; j++)
                    acc[i][j] = fmaf(a[i], bb[j], acc[i][j]);
        }
        __syncthreads();
    }

    #pragma unroll
    for (int i = 0; i < 8; i++) {
        int row = m0 + ty * 8 + i;
        float* cp = &C[(size_t)row * N + n0 + tx * 8];
        float4 v0 = make_float4(acc[i][0], acc[i][1], acc[i][2], acc[i][3]);
        float4 v1 = make_float4(acc[i][4], acc[i][5], acc[i][6], acc[i][7]);
        *(float4*)(cp + 0) = v0;
        *(float4*)(cp + 4) = v1;
    }
}

// ---------------------------------------------------------------------------
// Flash-style causal attention. One thread owns one query row.
// Q in registers, K/V tiles (64 x 64) in smem (broadcast reads).
// Online softmax in log2 domain; logits pre-scaled by (1/8)*log2(e).
// q/k/v layout: [b, s, h*64 + d]  (row stride DIMM)
// ---------------------------------------------------------------------------
#define BQ  128
#define BKT 64
#define CH  16

__global__ void __launch_bounds__(BQ) attn_causal()
{
    const int qt = blockIdx.x;
    const int h  = blockIdx.y;
    const int b  = blockIdx.z;
    const int qi = qt * BQ + threadIdx.x;

    const float SC = 0.125f * 1.4426950408889634f;   // (1/sqrt(64)) * log2(e)

    __shared__ float Ks[BKT][HD];
    __shared__ float Vs[BKT][HD];

    // load own Q row into registers
    float qreg[HD];
    {
        const float* qp = &g_q[(size_t)(b * SEQ + qi) * DIMM + h * HD];
        #pragma unroll
        for (int d = 0; d < HD; d += 4) {
            float4 t = *(const float4*)&qp[d];
            qreg[d + 0] = t.x; qreg[d + 1] = t.y;
            qreg[d + 2] = t.z; qreg[d + 3] = t.w;
        }
    }

    float o[HD];
    #pragma unroll
    for (int d = 0; d < HD; d++) o[d] = 0.0f;
    float mv = -INFINITY;
    float l  = 0.0f;

    const int kmax = qt * BQ + BQ;   // exclusive upper bound on keys this block needs

    for (int k0 = 0; k0 < kmax; k0 += BKT) {
        // cooperative K/V tile load
        for (int i = threadIdx.x; i < (BKT * HD) / 4; i += BQ) {
            int kk = i >> 4;            // / (HD/4)
            int d  = (i & 15) << 2;
            size_t gidx = (size_t)(b * SEQ + k0 + kk) * DIMM + h * HD + d;
            *(float4*)&Ks[kk][d] = *(const float4*)&g_k[gidx];
            *(float4*)&Vs[kk][d] = *(const float4*)&g_v[gidx];
        }
        __syncthreads();

        #pragma unroll 1
        for (int c = 0; c < BKT; c += CH) {
            float s[CH];
            float cm = -INFINITY;
            #pragma unroll
            for (int j = 0; j < CH; j++) {
                int kk = c + j;
                float a0 = 0.f, a1 = 0.f, a2 = 0.f, a3 = 0.f;
                #pragma unroll
                for (int d = 0; d < HD; d += 4) {
                    a0 = fmaf(qreg[d + 0], Ks[kk][d + 0], a0);
                    a1 = fmaf(qreg[d + 1], Ks[kk][d + 1], a1);
                    a2 = fmaf(qreg[d + 2], Ks[kk][d + 2], a2);
                    a3 = fmaf(qreg[d + 3], Ks[kk][d + 3], a3);
                }
                float sv = ((a0 + a1) + (a2 + a3)) * SC;
                sv = (k0 + kk <= qi) ? sv : -INFINITY;
                cm = fmaxf(cm, sv);
                s[j] = sv;
            }
            if (cm == -INFINITY) continue;   // whole chunk masked for this row

            float mnew = fmaxf(mv, cm);
            float corr = fast_exp2(mv - mnew);   // mv=-inf -> 0 (o is zero anyway)
            l *= corr;
            #pragma unroll
            for (int d = 0; d < HD; d++) o[d] *= corr;

            #pragma unroll
            for (int j = 0; j < CH; j++) {
                float p = fast_exp2(s[j] - mnew);   // masked -> exp2(-inf) = 0
                l += p;
                int kk = c + j;
                #pragma unroll
                for (int d = 0; d < HD; d++)
                    o[d] = fmaf(p, Vs[kk][d], o[d]);
            }
            mv = mnew;
        }
        __syncthreads();
    }

    const float inv = 1.0f / l;
    float* op = &g_ctx[(size_t)(b * SEQ + qi) * DIMM + h * HD];
    #pragma unroll
    for (int d = 0; d < HD; d += 4) {
        float4 t = make_float4(o[d] * inv, o[d + 1] * inv, o[d + 2] * inv, o[d + 3] * inv);
        *(float4*)&op[d] = t;
    }
}

// ---------------------------------------------------------------------------

extern "C" void kernel_launch(void* const* d_in, const int* in_sizes, int n_in,
                              void* d_out, int out_size)
{
    const float* x  = (const float*)d_in[0];
    const float* wq = (const float*)d_in[1];
    const float* wk = (const float*)d_in[2];
    const float* wv = (const float*)d_in[3];
    const float* wo = (const float*)d_in[4];
    float* out = (float*)d_out;

    float* gq;  cudaGetSymbolAddress((void**)&gq,  g_q);
    float* gk;  cudaGetSymbolAddress((void**)&gk,  g_k);
    float* gv;  cudaGetSymbolAddress((void**)&gv,  g_v);
    float* gc;  cudaGetSymbolAddress((void**)&gc,  g_ctx);

    dim3 gblk(256);
    dim3 ggrid(1024 / 128, MTOT / 128);   // (8, 32)

    gemm_awT<<<ggrid, gblk>>>(x, wq, gq);
    gemm_awT<<<ggrid, gblk>>>(x, wk, gk);
    gemm_awT<<<ggrid, gblk>>>(x, wv, gv);

    dim3 agrid(SEQ / BQ, NH, BATCHN);     // (16, 16, 2)
    attn_causal<<<agrid, BQ>>>();

    gemm_awT<<<ggrid, gblk>>>(gc, wo, out);
}

// round 3
// speedup vs baseline: 1.3103x; 1.3103x over previous
#include <cuda_runtime.h>
#include <cuda_bf16.h>
#include <cstdint>
#include <math.h>

#define DIN   1024
#define DIMM  1024
#define NH    16
#define HD    64
#define SEQ   2048
#define BATCHN 2
#define MTOT  (BATCHN*SEQ)   // 4096
#define K3    3072           // 3x split along K

// ---------------------------------------------------------------------------
// Scratch (allocation-free rule: __device__ globals)
// ---------------------------------------------------------------------------
__device__ __align__(16) float g_q[MTOT*DIMM];
__device__ __align__(16) float g_k[MTOT*DIMM];
__device__ __align__(16) float g_v[MTOT*DIMM];
__device__ __align__(16) float g_ctx[MTOT*DIMM];

__device__ __align__(16) __nv_bfloat16 g_x3 [MTOT*K3];
__device__ __align__(16) __nv_bfloat16 g_c3 [MTOT*K3];
__device__ __align__(16) __nv_bfloat16 g_wq3[DIMM*K3];
__device__ __align__(16) __nv_bfloat16 g_wk3[DIMM*K3];
__device__ __align__(16) __nv_bfloat16 g_wv3[DIMM*K3];
__device__ __align__(16) __nv_bfloat16 g_wo3[DIMM*K3];

__device__ __forceinline__ uint32_t smem_to_u32(const void* smem_ptr) {
    uint32_t addr;
    asm("{ .reg .u64 tmp; cvta.to.shared.u64 tmp, %1; cvt.u32.u64 %0, tmp; }"
        : "=r"(addr) : "l"(smem_ptr));
    return addr;
}

__device__ __forceinline__ float fast_exp2(float x) {
    float y;
    asm("ex2.approx.ftz.f32 %0, %1;" : "=f"(y) : "f"(x));
    return y;
}

// ---------------------------------------------------------------------------
// fp32 -> bf16x3 split along K.
// aPattern=1 (activations): segments [hi, mid, hi]
// aPattern=0 (weights):     segments [hi, hi,  mid]
// Dot(A',B') over K3 = Ah*Bh + Am*Bh + Ah*Bm  ~= fp32 product (err ~1e-5)
// ---------------------------------------------------------------------------
__global__ void __launch_bounds__(256) split3(const float* __restrict__ src,
                                              __nv_bfloat16* __restrict__ dst,
                                              int aPattern)
{
    int idx = blockIdx.x * blockDim.x + threadIdx.x;   // over rows*1024
    int r = idx >> 10;
    int c = idx & 1023;
    float f = src[idx];
    __nv_bfloat16 hi  = __float2bfloat16(f);
    __nv_bfloat16 mid = __float2bfloat16(f - __bfloat162float(hi));
    size_t base = (size_t)r * K3;
    if (aPattern) {
        dst[base + c]        = hi;
        dst[base + 1024 + c] = mid;
        dst[base + 2048 + c] = hi;
    } else {
        dst[base + c]        = hi;
        dst[base + 1024 + c] = hi;
        dst[base + 2048 + c] = mid;
    }
}

// ---------------------------------------------------------------------------
// HMMA GEMM: C[4096,1024](f32) = A'[4096,3072](bf16) @ B'[1024,3072](bf16)^T
// mma.sync.m16n8k16, 128x128 block tile, BK=32, 8 warps (64x32 warp tiles),
// 3-stage cp.async pipeline, padded smem stride 40 halves (ldmatrix
// conflict-free), ldmatrix.x4 fragment loads.
// ---------------------------------------------------------------------------
#define GS      3
#define BK      32
#define GKIT    (K3 / BK)          // 96
#define STRIDE  40                 // halves per smem row (32 + 8 pad)
#define TILE_HALVES (128 * STRIDE) // per A or B tile
#define STAGE_HALVES (2 * TILE_HALVES)
#define GEMM_SMEM (GS * STAGE_HALVES * 2)   // bytes = 3*20480 = 61440

__device__ __forceinline__ void ldsm_x4(uint32_t& r0, uint32_t& r1,
                                        uint32_t& r2, uint32_t& r3, uint32_t addr) {
    asm volatile("ldmatrix.sync.aligned.m8n8.x4.shared.b16 {%0,%1,%2,%3}, [%4];"
        : "=r"(r0), "=r"(r1), "=r"(r2), "=r"(r3) : "r"(addr));
}

__device__ __forceinline__ void mma16816(float* c, uint32_t a0, uint32_t a1,
                                         uint32_t a2, uint32_t a3,
                                         uint32_t b0, uint32_t b1) {
    asm volatile(
        "mma.sync.aligned.m16n8k16.row.col.f32.bf16.bf16.f32 "
        "{%0,%1,%2,%3}, {%4,%5,%6,%7}, {%8,%9}, {%0,%1,%2,%3};"
        : "+f"(c[0]), "+f"(c[1]), "+f"(c[2]), "+f"(c[3])
        : "r"(a0), "r"(a1), "r"(a2), "r"(a3), "r"(b0), "r"(b1));
}

__device__ __forceinline__ void gemm_fill_stage(
    uint32_t sm_base, int stage, int iter, int tid, int m0, int n0,
    const __nv_bfloat16* __restrict__ Ag, const __nv_bfloat16* __restrict__ Bg)
{
    const int k0 = iter * BK;
    const uint32_t stage_base = sm_base + stage * (STAGE_HALVES * 2);
    // A: 512 16B-chunks, B: 512 16B-chunks; 256 threads x 4 chunks.
    #pragma unroll
    for (int t = 0; t < 2; t++) {
        int c   = tid + t * 256;       // 0..511
        int row = c >> 2;              // 0..127
        int kc  = (c & 3) * 8;         // half offset within BK
        const __nv_bfloat16* srcA = &Ag[(size_t)(m0 + row) * K3 + k0 + kc];
        const __nv_bfloat16* srcB = &Bg[(size_t)(n0 + row) * K3 + k0 + kc];
        uint32_t dstA = stage_base + (row * STRIDE + kc) * 2;
        uint32_t dstB = dstA + TILE_HALVES * 2;
        asm volatile("cp.async.cg.shared.global [%0], [%1], 16;" :: "r"(dstA), "l"(srcA) : "memory");
        asm volatile("cp.async.cg.shared.global [%0], [%1], 16;" :: "r"(dstB), "l"(srcB) : "memory");
    }
    asm volatile("cp.async.commit_group;" ::: "memory");
}

__global__ void __launch_bounds__(256, 1) gemm_mma(const __nv_bfloat16* __restrict__ Ag,
                                                   const __nv_bfloat16* __restrict__ Bg,
                                                   float* __restrict__ C)
{
    extern __shared__ char smem[];
    const uint32_t sm_base = smem_to_u32(smem);
    const int tid  = threadIdx.x;
    const int wid  = tid >> 5;
    const int lane = tid & 31;
    const int m0 = blockIdx.y * 128;
    const int n0 = blockIdx.x * 128;

    const int wm = (wid >> 2) * 64;    // warp M offset in tile (0 or 64)
    const int wn = (wid & 3) * 32;     // warp N offset in tile (0..96)

    const int q = lane >> 3;           // 0..3 (ldmatrix sub-matrix)
    const int r = lane & 7;            // 0..7

    float acc[4][4][4];
    #pragma unroll
    for (int mi = 0; mi < 4; mi++)
        #pragma unroll
        for (int ni = 0; ni < 4; ni++)
            #pragma unroll
            for (int e = 0; e < 4; e++) acc[mi][ni][e] = 0.0f;

    // prologue
    #pragma unroll
    for (int s = 0; s < GS - 1; s++)
        gemm_fill_stage(sm_base, s, s, tid, m0, n0, Ag, Bg);

    for (int i = 0; i < GKIT; i++) {
        asm volatile("cp.async.wait_group %0;" :: "n"(GS - 2) : "memory");
        __syncthreads();

        const int j = i + GS - 1;
        if (j < GKIT)
            gemm_fill_stage(sm_base, j % GS, j, tid, m0, n0, Ag, Bg);

        const uint32_t stage_base = sm_base + (i % GS) * (STAGE_HALVES * 2);
        const uint32_t bbase = stage_base + TILE_HALVES * 2;

        #pragma unroll
        for (int ks = 0; ks < 2; ks++) {
            const int kh = ks * 16;
            uint32_t af[4][4];
            #pragma unroll
            for (int mi = 0; mi < 4; mi++) {
                int arow = wm + mi * 16 + (q & 1) * 8 + r;
                int acol = kh + (q >> 1) * 8;
                ldsm_x4(af[mi][0], af[mi][1], af[mi][2], af[mi][3],
                        stage_base + (arow * STRIDE + acol) * 2);
            }
            uint32_t bf[4][2];
            #pragma unroll
            for (int p = 0; p < 2; p++) {   // each covers 2 n-frags (16 n)
                int brow = wn + p * 16 + (q >> 1) * 8 + r;
                int bcol = kh + (q & 1) * 8;
                uint32_t b0, b1, b2, b3;
                ldsm_x4(b0, b1, b2, b3, bbase + (brow * STRIDE + bcol) * 2);
                bf[p * 2 + 0][0] = b0; bf[p * 2 + 0][1] = b1;
                bf[p * 2 + 1][0] = b2; bf[p * 2 + 1][1] = b3;
            }
            #pragma unroll
            for (int mi = 0; mi < 4; mi++)
                #pragma unroll
                for (int ni = 0; ni < 4; ni++)
                    mma16816(acc[mi][ni], af[mi][0], af[mi][1], af[mi][2], af[mi][3],
                             bf[ni][0], bf[ni][1]);
        }
        __syncthreads();
    }

    // epilogue: c0/c1 -> row groupID, c2/c3 -> row groupID+8
    const int gp = lane >> 2;       // 0..7
    const int t4 = lane & 3;        // 0..3
    #pragma unroll
    for (int mi = 0; mi < 4; mi++) {
        int row0 = m0 + wm + mi * 16 + gp;
        #pragma unroll
        for (int ni = 0; ni < 4; ni++) {
            int col = n0 + wn + ni * 8 + t4 * 2;
            float2 v0 = make_float2(acc[mi][ni][0], acc[mi][ni][1]);
            float2 v1 = make_float2(acc[mi][ni][2], acc[mi][ni][3]);
            *(float2*)&C[(size_t)row0 * 1024 + col]       = v0;
            *(float2*)&C[(size_t)(row0 + 8) * 1024 + col] = v1;
        }
    }
}

// ---------------------------------------------------------------------------
// Flash-style causal attention (unchanged). One thread per query row.
// ---------------------------------------------------------------------------
#define BQ  128
#define BKT 64
#define CH  16

__global__ void __launch_bounds__(BQ) attn_causal()
{
    const int qt = blockIdx.x;
    const int h  = blockIdx.y;
    const int b  = blockIdx.z;
    const int qi = qt * BQ + threadIdx.x;

    const float SC = 0.125f * 1.4426950408889634f;

    __shared__ float Ks[BKT][HD];
    __shared__ float Vs[BKT][HD];

    float qreg[HD];
    {
        const float* qp = &g_q[(size_t)(b * SEQ + qi) * DIMM + h * HD];
        #pragma unroll
        for (int d = 0; d < HD; d += 4) {
            float4 t = *(const float4*)&qp[d];
            qreg[d + 0] = t.x; qreg[d + 1] = t.y;
            qreg[d + 2] = t.z; qreg[d + 3] = t.w;
        }
    }

    float o[HD];
    #pragma unroll
    for (int d = 0; d < HD; d++) o[d] = 0.0f;
    float mv = -INFINITY;
    float l  = 0.0f;

    const int kmax = qt * BQ + BQ;

    for (int k0 = 0; k0 < kmax; k0 += BKT) {
        for (int i = threadIdx.x; i < (BKT * HD) / 4; i += BQ) {
            int kk = i >> 4;
            int d  = (i & 15) << 2;
            size_t gidx = (size_t)(b * SEQ + k0 + kk) * DIMM + h * HD + d;
            *(float4*)&Ks[kk][d] = *(const float4*)&g_k[gidx];
            *(float4*)&Vs[kk][d] = *(const float4*)&g_v[gidx];
        }
        __syncthreads();

        #pragma unroll 1
        for (int c = 0; c < BKT; c += CH) {
            float s[CH];
            float cm = -INFINITY;
            #pragma unroll
            for (int j = 0; j < CH; j++) {
                int kk = c + j;
                float a0 = 0.f, a1 = 0.f, a2 = 0.f, a3 = 0.f;
                #pragma unroll
                for (int d = 0; d < HD; d += 4) {
                    a0 = fmaf(qreg[d + 0], Ks[kk][d + 0], a0);
                    a1 = fmaf(qreg[d + 1], Ks[kk][d + 1], a1);
                    a2 = fmaf(qreg[d + 2], Ks[kk][d + 2], a2);
                    a3 = fmaf(qreg[d + 3], Ks[kk][d + 3], a3);
                }
                float sv = ((a0 + a1) + (a2 + a3)) * SC;
                sv = (k0 + kk <= qi) ? sv : -INFINITY;
                cm = fmaxf(cm, sv);
                s[j] = sv;
            }
            if (cm == -INFINITY) continue;

            float mnew = fmaxf(mv, cm);
            float corr = fast_exp2(mv - mnew);
            l *= corr;
            #pragma unroll
            for (int d = 0; d < HD; d++) o[d] *= corr;

            #pragma unroll
            for (int j = 0; j < CH; j++) {
                float p = fast_exp2(s[j] - mnew);
                l += p;
                int kk = c + j;
                #pragma unroll
                for (int d = 0; d < HD; d++)
                    o[d] = fmaf(p, Vs[kk][d], o[d]);
            }
            mv = mnew;
        }
        __syncthreads();
    }

    const float inv = 1.0f / l;
    float* op = &g_ctx[(size_t)(b * SEQ + qi) * DIMM + h * HD];
    #pragma unroll
    for (int d = 0; d < HD; d += 4) {
        float4 t = make_float4(o[d] * inv, o[d + 1] * inv, o[d + 2] * inv, o[d + 3] * inv);
        *(float4*)&op[d] = t;
    }
}

// ---------------------------------------------------------------------------

extern "C" void kernel_launch(void* const* d_in, const int* in_sizes, int n_in,
                              void* d_out, int out_size)
{
    const float* x  = (const float*)d_in[0];
    const float* wq = (const float*)d_in[1];
    const float* wk = (const float*)d_in[2];
    const float* wv = (const float*)d_in[3];
    const float* wo = (const float*)d_in[4];
    float* out = (float*)d_out;

    float* gq;  cudaGetSymbolAddress((void**)&gq,  g_q);
    float* gk;  cudaGetSymbolAddress((void**)&gk,  g_k);
    float* gv;  cudaGetSymbolAddress((void**)&gv,  g_v);
    float* gc;  cudaGetSymbolAddress((void**)&gc,  g_ctx);
    __nv_bfloat16 *x3, *c3, *wq3, *wk3, *wv3, *wo3;
    cudaGetSymbolAddress((void**)&x3,  g_x3);
    cudaGetSymbolAddress((void**)&c3,  g_c3);
    cudaGetSymbolAddress((void**)&wq3, g_wq3);
    cudaGetSymbolAddress((void**)&wk3, g_wk3);
    cudaGetSymbolAddress((void**)&wv3, g_wv3);
    cudaGetSymbolAddress((void**)&wo3, g_wo3);

    cudaFuncSetAttribute(gemm_mma, cudaFuncAttributeMaxDynamicSharedMemorySize, GEMM_SMEM);

    split3<<<(MTOT*1024)/256, 256>>>(x,  x3,  1);
    split3<<<(DIMM*1024)/256, 256>>>(wq, wq3, 0);
    split3<<<(DIMM*1024)/256, 256>>>(wk, wk3, 0);
    split3<<<(DIMM*1024)/256, 256>>>(wv, wv3, 0);
    split3<<<(DIMM*1024)/256, 256>>>(wo, wo3, 0);

    dim3 ggrid(1024 / 128, MTOT / 128);   // (8, 32)
    gemm_mma<<<ggrid, 256, GEMM_SMEM>>>(x3, wq3, gq);
    gemm_mma<<<ggrid, 256, GEMM_SMEM>>>(x3, wk3, gk);
    gemm_mma<<<ggrid, 256, GEMM_SMEM>>>(x3, wv3, gv);

    dim3 agrid(SEQ / BQ, NH, BATCHN);     // (16, 16, 2)
    attn_causal<<<agrid, BQ>>>();

    split3<<<(MTOT*1024)/256, 256>>>(gc, c3, 1);
    gemm_mma<<<ggrid, 256, GEMM_SMEM>>>(c3, wo3, out);
}

// round 4
// speedup vs baseline: 3.0632x; 2.3379x over previous
#include <cuda_runtime.h>
#include <cuda_bf16.h>
#include <cuda_fp16.h>
#include <cstdint>
#include <math.h>

#define DIN   1024
#define DIMM  1024
#define NH    16
#define HD    64
#define SEQ   2048
#define BATCHN 2
#define MTOT  (BATCHN*SEQ)   // 4096
#define K3    3072           // 3x split along K

// ---------------------------------------------------------------------------
// Scratch (allocation-free rule: __device__ globals)
// ---------------------------------------------------------------------------
__device__ __align__(16) float g_q[MTOT*DIMM];
__device__ __align__(16) float g_k[MTOT*DIMM];
__device__ __align__(16) float g_v[MTOT*DIMM];
__device__ __align__(16) float g_ctx[MTOT*DIMM];

__device__ __align__(16) __half g_q16[MTOT*DIMM];
__device__ __align__(16) __half g_k16[MTOT*DIMM];
__device__ __align__(16) __half g_v16[MTOT*DIMM];

__device__ __align__(16) __nv_bfloat16 g_x3 [MTOT*K3];
__device__ __align__(16) __nv_bfloat16 g_c3 [MTOT*K3];
__device__ __align__(16) __nv_bfloat16 g_wq3[DIMM*K3];
__device__ __align__(16) __nv_bfloat16 g_wk3[DIMM*K3];
__device__ __align__(16) __nv_bfloat16 g_wv3[DIMM*K3];
__device__ __align__(16) __nv_bfloat16 g_wo3[DIMM*K3];

__device__ __forceinline__ uint32_t smem_to_u32(const void* smem_ptr) {
    uint32_t addr;
    asm("{ .reg .u64 tmp; cvta.to.shared.u64 tmp, %1; cvt.u32.u64 %0, tmp; }"
        : "=r"(addr) : "l"(smem_ptr));
    return addr;
}

__device__ __forceinline__ float fast_exp2(float x) {
    float y;
    asm("ex2.approx.ftz.f32 %0, %1;" : "=f"(y) : "f"(x));
    return y;
}

__device__ __forceinline__ void ldsm_x4(uint32_t& r0, uint32_t& r1,
                                        uint32_t& r2, uint32_t& r3, uint32_t addr) {
    asm volatile("ldmatrix.sync.aligned.m8n8.x4.shared.b16 {%0,%1,%2,%3}, [%4];"
        : "=r"(r0), "=r"(r1), "=r"(r2), "=r"(r3) : "r"(addr));
}

__device__ __forceinline__ void ldsm_x4_t(uint32_t& r0, uint32_t& r1,
                                          uint32_t& r2, uint32_t& r3, uint32_t addr) {
    asm volatile("ldmatrix.sync.aligned.m8n8.x4.trans.shared.b16 {%0,%1,%2,%3}, [%4];"
        : "=r"(r0), "=r"(r1), "=r"(r2), "=r"(r3) : "r"(addr));
}

__device__ __forceinline__ void mma16816(float* c, uint32_t a0, uint32_t a1,
                                         uint32_t a2, uint32_t a3,
                                         uint32_t b0, uint32_t b1) {
    asm volatile(
        "mma.sync.aligned.m16n8k16.row.col.f32.bf16.bf16.f32 "
        "{%0,%1,%2,%3}, {%4,%5,%6,%7}, {%8,%9}, {%0,%1,%2,%3};"
        : "+f"(c[0]), "+f"(c[1]), "+f"(c[2]), "+f"(c[3])
        : "r"(a0), "r"(a1), "r"(a2), "r"(a3), "r"(b0), "r"(b1));
}

__device__ __forceinline__ void mma16816h(float* c, uint32_t a0, uint32_t a1,
                                          uint32_t a2, uint32_t a3,
                                          uint32_t b0, uint32_t b1) {
    asm volatile(
        "mma.sync.aligned.m16n8k16.row.col.f32.f16.f16.f32 "
        "{%0,%1,%2,%3}, {%4,%5,%6,%7}, {%8,%9}, {%0,%1,%2,%3};"
        : "+f"(c[0]), "+f"(c[1]), "+f"(c[2]), "+f"(c[3])
        : "r"(a0), "r"(a1), "r"(a2), "r"(a3), "r"(b0), "r"(b1));
}

#define CP_ASYNC16(dst, src) \
    asm volatile("cp.async.cg.shared.global [%0], [%1], 16;" :: "r"(dst), "l"(src) : "memory")
#define CP_COMMIT() asm volatile("cp.async.commit_group;" ::: "memory")
#define CP_WAIT0()  asm volatile("cp.async.wait_group 0;" ::: "memory")

// ---------------------------------------------------------------------------
// fp32 -> bf16x3 split along K (for linear layers).
// ---------------------------------------------------------------------------
__global__ void __launch_bounds__(256) split3(const float* __restrict__ src,
                                              __nv_bfloat16* __restrict__ dst,
                                              int aPattern)
{
    int idx = blockIdx.x * blockDim.x + threadIdx.x;
    int r = idx >> 10;
    int c = idx & 1023;
    float f = src[idx];
    __nv_bfloat16 hi  = __float2bfloat16(f);
    __nv_bfloat16 mid = __float2bfloat16(f - __bfloat162float(hi));
    size_t base = (size_t)r * K3;
    if (aPattern) {
        dst[base + c]        = hi;
        dst[base + 1024 + c] = mid;
        dst[base + 2048 + c] = hi;
    } else {
        dst[base + c]        = hi;
        dst[base + 1024 + c] = hi;
        dst[base + 2048 + c] = mid;
    }
}

// ---------------------------------------------------------------------------
// fp32 q/k/v -> fp16 (q pre-scaled by (1/8)*log2(e) so QK logits land in
// log2 domain directly).
// ---------------------------------------------------------------------------
__global__ void __launch_bounds__(256) cvt_qkv()
{
    const float S = 0.18033688011112042f;   // 0.125 * log2(e)
    int idx = (blockIdx.x * 256 + threadIdx.x) * 4;
    float4 q = *(const float4*)&g_q[idx];
    float4 k = *(const float4*)&g_k[idx];
    float4 v = *(const float4*)&g_v[idx];
    *(__half2*)&g_q16[idx]     = __floats2half2_rn(q.x * S, q.y * S);
    *(__half2*)&g_q16[idx + 2] = __floats2half2_rn(q.z * S, q.w * S);
    *(__half2*)&g_k16[idx]     = __floats2half2_rn(k.x, k.y);
    *(__half2*)&g_k16[idx + 2] = __floats2half2_rn(k.z, k.w);
    *(__half2*)&g_v16[idx]     = __floats2half2_rn(v.x, v.y);
    *(__half2*)&g_v16[idx + 2] = __floats2half2_rn(v.z, v.w);
}

// ---------------------------------------------------------------------------
// HMMA GEMM: C[4096,1024](f32) = A'[4096,3072](bf16) @ B'[1024,3072](bf16)^T
// (unchanged from R3)
// ---------------------------------------------------------------------------
#define GS      3
#define BK      32
#define GKIT    (K3 / BK)
#define STRIDE  40
#define TILE_HALVES (128 * STRIDE)
#define STAGE_HALVES (2 * TILE_HALVES)
#define GEMM_SMEM (GS * STAGE_HALVES * 2)

__device__ __forceinline__ void gemm_fill_stage(
    uint32_t sm_base, int stage, int iter, int tid, int m0, int n0,
    const __nv_bfloat16* __restrict__ Ag, const __nv_bfloat16* __restrict__ Bg)
{
    const int k0 = iter * BK;
    const uint32_t stage_base = sm_base + stage * (STAGE_HALVES * 2);
    #pragma unroll
    for (int t = 0; t < 2; t++) {
        int c   = tid + t * 256;
        int row = c >> 2;
        int kc  = (c & 3) * 8;
        const __nv_bfloat16* srcA = &Ag[(size_t)(m0 + row) * K3 + k0 + kc];
        const __nv_bfloat16* srcB = &Bg[(size_t)(n0 + row) * K3 + k0 + kc];
        uint32_t dstA = stage_base + (row * STRIDE + kc) * 2;
        uint32_t dstB = dstA + TILE_HALVES * 2;
        CP_ASYNC16(dstA, srcA);
        CP_ASYNC16(dstB, srcB);
    }
    CP_COMMIT();
}

__global__ void __launch_bounds__(256, 1) gemm_mma(const __nv_bfloat16* __restrict__ Ag,
                                                   const __nv_bfloat16* __restrict__ Bg,
                                                   float* __restrict__ C)
{
    extern __shared__ char smem[];
    const uint32_t sm_base = smem_to_u32(smem);
    const int tid  = threadIdx.x;
    const int wid  = tid >> 5;
    const int lane = tid & 31;
    const int m0 = blockIdx.y * 128;
    const int n0 = blockIdx.x * 128;

    const int wm = (wid >> 2) * 64;
    const int wn = (wid & 3) * 32;

    const int q = lane >> 3;
    const int r = lane & 7;

    float acc[4][4][4];
    #pragma unroll
    for (int mi = 0; mi < 4; mi++)
        #pragma unroll
        for (int ni = 0; ni < 4; ni++)
            #pragma unroll
            for (int e = 0; e < 4; e++) acc[mi][ni][e] = 0.0f;

    #pragma unroll
    for (int s = 0; s < GS - 1; s++)
        gemm_fill_stage(sm_base, s, s, tid, m0, n0, Ag, Bg);

    for (int i = 0; i < GKIT; i++) {
        asm volatile("cp.async.wait_group %0;" :: "n"(GS - 2) : "memory");
        __syncthreads();

        const int j = i + GS - 1;
        if (j < GKIT)
            gemm_fill_stage(sm_base, j % GS, j, tid, m0, n0, Ag, Bg);

        const uint32_t stage_base = sm_base + (i % GS) * (STAGE_HALVES * 2);
        const uint32_t bbase = stage_base + TILE_HALVES * 2;

        #pragma unroll
        for (int ks = 0; ks < 2; ks++) {
            const int kh = ks * 16;
            uint32_t af[4][4];
            #pragma unroll
            for (int mi = 0; mi < 4; mi++) {
                int arow = wm + mi * 16 + (q & 1) * 8 + r;
                int acol = kh + (q >> 1) * 8;
                ldsm_x4(af[mi][0], af[mi][1], af[mi][2], af[mi][3],
                        stage_base + (arow * STRIDE + acol) * 2);
            }
            uint32_t bf[4][2];
            #pragma unroll
            for (int p = 0; p < 2; p++) {
                int brow = wn + p * 16 + (q >> 1) * 8 + r;
                int bcol = kh + (q & 1) * 8;
                uint32_t b0, b1, b2, b3;
                ldsm_x4(b0, b1, b2, b3, bbase + (brow * STRIDE + bcol) * 2);
                bf[p * 2 + 0][0] = b0; bf[p * 2 + 0][1] = b1;
                bf[p * 2 + 1][0] = b2; bf[p * 2 + 1][1] = b3;
            }
            #pragma unroll
            for (int mi = 0; mi < 4; mi++)
                #pragma unroll
                for (int ni = 0; ni < 4; ni++)
                    mma16816(acc[mi][ni], af[mi][0], af[mi][1], af[mi][2], af[mi][3],
                             bf[ni][0], bf[ni][1]);
        }
        __syncthreads();
    }

    const int gp = lane >> 2;
    const int t4 = lane & 3;
    #pragma unroll
    for (int mi = 0; mi < 4; mi++) {
        int row0 = m0 + wm + mi * 16 + gp;
        #pragma unroll
        for (int ni = 0; ni < 4; ni++) {
            int col = n0 + wn + ni * 8 + t4 * 2;
            float2 v0 = make_float2(acc[mi][ni][0], acc[mi][ni][1]);
            float2 v1 = make_float2(acc[mi][ni][2], acc[mi][ni][3]);
            *(float2*)&C[(size_t)row0 * 1024 + col]       = v0;
            *(float2*)&C[(size_t)(row0 + 8) * 1024 + col] = v1;
        }
    }
}

// ---------------------------------------------------------------------------
// Tensor-core flash attention (fp16 operands, fp32 accum, online softmax).
// Block = 64 q-rows of one (b,h); 4 warps, each owns 16 q-rows.
// KV tiles of 64, double-buffered via cp.async.
// Smem halves layout (stride 72): Q[64][72], P[64][72], K[2][64][72], V[2][64][72]
// ---------------------------------------------------------------------------
#define ASTR   72
#define ATILE_B (64 * ASTR * 2)          // 9216 bytes per tile
#define AQOFF  0
#define APOFF  (ATILE_B)
#define AKOFF  (2 * ATILE_B)
#define AVOFF  (4 * ATILE_B)
#define ATTN_SMEM (6 * ATILE_B)          // 55296
#define ABN   (-1e30f)

__device__ __forceinline__ void attn_prefetch(uint32_t smK, uint32_t smV,
                                              const __half* Kg, const __half* Vg,
                                              int tid)
{
    #pragma unroll
    for (int c = tid; c < 512; c += 128) {
        int row = c >> 3;
        int ch  = c & 7;
        uint32_t off = row * (ASTR * 2) + ch * 16;
        CP_ASYNC16(smK + off, Kg + (size_t)row * DIMM + ch * 8);
        CP_ASYNC16(smV + off, Vg + (size_t)row * DIMM + ch * 8);
    }
}

__global__ void __launch_bounds__(128) attn_mma()
{
    extern __shared__ char smem[];
    const uint32_t sm = smem_to_u32(smem);
    const int tid  = threadIdx.x;
    const int w    = tid >> 5;
    const int lane = tid & 31;
    const int gp   = lane >> 2;
    const int t4   = lane & 3;
    const int qt = gridDim.x - 1 - blockIdx.x;   // big q-tiles scheduled first
    const int h  = blockIdx.y;
    const int b  = blockIdx.z;

    const __half* Qg = g_q16 + (size_t)(b * SEQ + qt * 64) * DIMM + h * HD;
    const __half* Kg = g_k16 + (size_t)(b * SEQ) * DIMM + h * HD;
    const __half* Vg = g_v16 + (size_t)(b * SEQ) * DIMM + h * HD;

    // Q tile load (group 1)
    #pragma unroll
    for (int c = tid; c < 512; c += 128) {
        int row = c >> 3, ch = c & 7;
        CP_ASYNC16(sm + AQOFF + row * (ASTR * 2) + ch * 16,
                   Qg + (size_t)row * DIMM + ch * 8);
    }
    CP_COMMIT();
    // KV tile 0 (group 2)
    attn_prefetch(sm + AKOFF, sm + AVOFF, Kg, Vg, tid);
    CP_COMMIT();
    CP_WAIT0();
    __syncthreads();

    // hoist Q fragments (A operand, constant per block)
    uint32_t aQ[4][4];
    #pragma unroll
    for (int ks = 0; ks < 4; ks++)
        ldsm_x4(aQ[ks][0], aQ[ks][1], aQ[ks][2], aQ[ks][3],
                sm + AQOFF + ((w * 16 + (lane & 15)) * ASTR
                              + ks * 16 + (lane >> 4) * 8) * 2);

    float oacc[8][4];
    #pragma unroll
    for (int nf = 0; nf < 8; nf++)
        #pragma unroll
        for (int e = 0; e < 4; e++) oacc[nf][e] = 0.0f;
    float m0 = ABN, m1 = ABN, l0 = 0.0f, l1 = 0.0f;

    for (int t = 0; t <= qt; t++) {
        const uint32_t bufK = sm + AKOFF + (t & 1) * ATILE_B;
        const uint32_t bufV = sm + AVOFF + (t & 1) * ATILE_B;

        if (t > 0) { CP_WAIT0(); __syncthreads(); }
        if (t < qt) {
            attn_prefetch(sm + AKOFF + ((t + 1) & 1) * ATILE_B,
                          sm + AVOFF + ((t + 1) & 1) * ATILE_B,
                          Kg + (size_t)(t + 1) * 64 * DIMM,
                          Vg + (size_t)(t + 1) * 64 * DIMM, tid);
            CP_COMMIT();
        }

        // ---- S = Q @ K^T  (fp16 MMA, fp32 accum; logits already log2-scaled)
        float sacc[8][4];
        #pragma unroll
        for (int nf = 0; nf < 8; nf++)
            #pragma unroll
            for (int e = 0; e < 4; e++) sacc[nf][e] = 0.0f;

        #pragma unroll
        for (int ks = 0; ks < 4; ks++) {
            #pragma unroll
            for (int p = 0; p < 4; p++) {
                uint32_t b0, b1, b2, b3;
                int brow = p * 16 + (lane >> 4) * 8 + (lane & 7);
                int bcol = ks * 16 + ((lane >> 3) & 1) * 8;
                ldsm_x4(b0, b1, b2, b3, bufK + (brow * ASTR + bcol) * 2);
                mma16816h(sacc[2 * p],     aQ[ks][0], aQ[ks][1], aQ[ks][2], aQ[ks][3], b0, b1);
                mma16816h(sacc[2 * p + 1], aQ[ks][0], aQ[ks][1], aQ[ks][2], aQ[ks][3], b2, b3);
            }
        }

        // ---- causal mask (diagonal tile only)
        if (t == qt) {
            const int q0 = w * 16 + gp;      // local row index == local kv limit
            const int q1 = q0 + 8;
            #pragma unroll
            for (int nf = 0; nf < 8; nf++) {
                int c = nf * 8 + t4 * 2;
                if (c     > q0) sacc[nf][0] = ABN;
                if (c + 1 > q0) sacc[nf][1] = ABN;
                if (c     > q1) sacc[nf][2] = ABN;
                if (c + 1 > q1) sacc[nf][3] = ABN;
            }
        }

        // ---- online softmax
        float mx0 = ABN, mx1 = ABN;
        #pragma unroll
        for (int nf = 0; nf < 8; nf++) {
            mx0 = fmaxf(mx0, fmaxf(sacc[nf][0], sacc[nf][1]));
            mx1 = fmaxf(mx1, fmaxf(sacc[nf][2], sacc[nf][3]));
        }
        mx0 = fmaxf(mx0, __shfl_xor_sync(0xFFFFFFFF, mx0, 1));
        mx0 = fmaxf(mx0, __shfl_xor_sync(0xFFFFFFFF, mx0, 2));
        mx1 = fmaxf(mx1, __shfl_xor_sync(0xFFFFFFFF, mx1, 1));
        mx1 = fmaxf(mx1, __shfl_xor_sync(0xFFFFFFFF, mx1, 2));

        const float mn0 = fmaxf(m0, mx0);
        const float mn1 = fmaxf(m1, mx1);
        const float cr0 = fast_exp2(m0 - mn0);
        const float cr1 = fast_exp2(m1 - mn1);
        l0 *= cr0;  l1 *= cr1;
        m0 = mn0;   m1 = mn1;

        char* prow0 = smem + APOFF + ((w * 16 + gp) * ASTR + t4 * 2) * 2;
        char* prow1 = prow0 + 8 * ASTR * 2;
        #pragma unroll
        for (int nf = 0; nf < 8; nf++) {
            float p00 = fast_exp2(sacc[nf][0] - mn0);
            float p01 = fast_exp2(sacc[nf][1] - mn0);
            float p10 = fast_exp2(sacc[nf][2] - mn1);
            float p11 = fast_exp2(sacc[nf][3] - mn1);
            l0 += p00 + p01;
            l1 += p10 + p11;
            oacc[nf][0] *= cr0; oacc[nf][1] *= cr0;
            oacc[nf][2] *= cr1; oacc[nf][3] *= cr1;
            *(__half2*)(prow0 + nf * 16) = __floats2half2_rn(p00, p01);
            *(__half2*)(prow1 + nf * 16) = __floats2half2_rn(p10, p11);
        }
        __syncwarp();

        // ---- O += P @ V   (A = P rows [16w..), k = kv; B = V^T via ldmatrix.trans)
        #pragma unroll
        for (int ks = 0; ks < 4; ks++) {
            uint32_t a0, a1, a2, a3;
            ldsm_x4(a0, a1, a2, a3,
                    sm + APOFF + ((w * 16 + (lane & 15)) * ASTR
                                  + ks * 16 + (lane >> 4) * 8) * 2);
            #pragma unroll
            for (int p = 0; p < 4; p++) {
                uint32_t b0, b1, b2, b3;
                int vrow = ks * 16 + (lane & 15);
                int vcol = p * 16 + (lane >> 4) * 8;
                ldsm_x4_t(b0, b1, b2, b3, bufV + (vrow * ASTR + vcol) * 2);
                mma16816h(oacc[2 * p],     a0, a1, a2, a3, b0, b1);
                mma16816h(oacc[2 * p + 1], a0, a1, a2, a3, b2, b3);
            }
        }
    }

    // ---- epilogue
    l0 += __shfl_xor_sync(0xFFFFFFFF, l0, 1);
    l0 += __shfl_xor_sync(0xFFFFFFFF, l0, 2);
    l1 += __shfl_xor_sync(0xFFFFFFFF, l1, 1);
    l1 += __shfl_xor_sync(0xFFFFFFFF, l1, 2);
    const float inv0 = 1.0f / l0;
    const float inv1 = 1.0f / l1;

    const int qg = qt * 64 + w * 16 + gp;
    float* orow = g_ctx + (size_t)(b * SEQ + qg) * DIMM + h * HD;
    #pragma unroll
    for (int nf = 0; nf < 8; nf++) {
        int col = nf * 8 + t4 * 2;
        *(float2*)(orow + col)            = make_float2(oacc[nf][0] * inv0, oacc[nf][1] * inv0);
        *(float2*)(orow + 8 * DIMM + col) = make_float2(oacc[nf][2] * inv1, oacc[nf][3] * inv1);
    }
}

// ---------------------------------------------------------------------------

extern "C" void kernel_launch(void* const* d_in, const int* in_sizes, int n_in,
                              void* d_out, int out_size)
{
    const float* x  = (const float*)d_in[0];
    const float* wq = (const float*)d_in[1];
    const float* wk = (const float*)d_in[2];
    const float* wv = (const float*)d_in[3];
    const float* wo = (const float*)d_in[4];
    float* out = (float*)d_out;

    float* gq;  cudaGetSymbolAddress((void**)&gq,  g_q);
    float* gk;  cudaGetSymbolAddress((void**)&gk,  g_k);
    float* gv;  cudaGetSymbolAddress((void**)&gv,  g_v);
    float* gc;  cudaGetSymbolAddress((void**)&gc,  g_ctx);
    __nv_bfloat16 *x3, *c3, *wq3, *wk3, *wv3, *wo3;
    cudaGetSymbolAddress((void**)&x3,  g_x3);
    cudaGetSymbolAddress((void**)&c3,  g_c3);
    cudaGetSymbolAddress((void**)&wq3, g_wq3);
    cudaGetSymbolAddress((void**)&wk3, g_wk3);
    cudaGetSymbolAddress((void**)&wv3, g_wv3);
    cudaGetSymbolAddress((void**)&wo3, g_wo3);

    cudaFuncSetAttribute(gemm_mma, cudaFuncAttributeMaxDynamicSharedMemorySize, GEMM_SMEM);
    cudaFuncSetAttribute(attn_mma, cudaFuncAttributeMaxDynamicSharedMemorySize, ATTN_SMEM);

    split3<<<(MTOT*1024)/256, 256>>>(x,  x3,  1);
    split3<<<(DIMM*1024)/256, 256>>>(wq, wq3, 0);
    split3<<<(DIMM*1024)/256, 256>>>(wk, wk3, 0);
    split3<<<(DIMM*1024)/256, 256>>>(wv, wv3, 0);
    split3<<<(DIMM*1024)/256, 256>>>(wo, wo3, 0);

    dim3 ggrid(1024 / 128, MTOT / 128);   // (8, 32)
    gemm_mma<<<ggrid, 256, GEMM_SMEM>>>(x3, wq3, gq);
    gemm_mma<<<ggrid, 256, GEMM_SMEM>>>(x3, wk3, gk);
    gemm_mma<<<ggrid, 256, GEMM_SMEM>>>(x3, wv3, gv);

    cvt_qkv<<<(MTOT*DIMM)/(256*4), 256>>>();

    dim3 agrid(SEQ / 64, NH, BATCHN);     // (32, 16, 2)
    attn_mma<<<agrid, 128, ATTN_SMEM>>>();

    split3<<<(MTOT*1024)/256, 256>>>(gc, c3, 1);
    gemm_mma<<<ggrid, 256, GEMM_SMEM>>>(c3, wo3, out);
}

// round 5
// speedup vs baseline: 6.8805x; 2.2462x over previous
#include <cuda_runtime.h>
#include <cuda_fp16.h>
#include <cstdint>
#include <math.h>

#define DIN   1024
#define DIMM  1024
#define NH    16
#define HD    64
#define SEQ   2048
#define BATCHN 2
#define MTOT  (BATCHN*SEQ)   // 4096
#define KD    1024

// ---------------------------------------------------------------------------
// Scratch (allocation-free rule: __device__ globals)
// ---------------------------------------------------------------------------
__device__ __align__(16) __half g_x16[MTOT*DIMM];
__device__ __align__(16) __half g_q16[MTOT*DIMM];
__device__ __align__(16) __half g_k16[MTOT*DIMM];
__device__ __align__(16) __half g_v16[MTOT*DIMM];
__device__ __align__(16) __half g_c16[MTOT*DIMM];
__device__ __align__(16) __half g_wq16[DIMM*DIMM];
__device__ __align__(16) __half g_wk16[DIMM*DIMM];
__device__ __align__(16) __half g_wv16[DIMM*DIMM];
__device__ __align__(16) __half g_wo16[DIMM*DIMM];

__device__ __forceinline__ uint32_t smem_to_u32(const void* smem_ptr) {
    uint32_t addr;
    asm("{ .reg .u64 tmp; cvta.to.shared.u64 tmp, %1; cvt.u32.u64 %0, tmp; }"
        : "=r"(addr) : "l"(smem_ptr));
    return addr;
}

__device__ __forceinline__ float fast_exp2(float x) {
    float y;
    asm("ex2.approx.ftz.f32 %0, %1;" : "=f"(y) : "f"(x));
    return y;
}

__device__ __forceinline__ void ldsm_x4(uint32_t& r0, uint32_t& r1,
                                        uint32_t& r2, uint32_t& r3, uint32_t addr) {
    asm volatile("ldmatrix.sync.aligned.m8n8.x4.shared.b16 {%0,%1,%2,%3}, [%4];"
        : "=r"(r0), "=r"(r1), "=r"(r2), "=r"(r3) : "r"(addr));
}

__device__ __forceinline__ void ldsm_x4_t(uint32_t& r0, uint32_t& r1,
                                          uint32_t& r2, uint32_t& r3, uint32_t addr) {
    asm volatile("ldmatrix.sync.aligned.m8n8.x4.trans.shared.b16 {%0,%1,%2,%3}, [%4];"
        : "=r"(r0), "=r"(r1), "=r"(r2), "=r"(r3) : "r"(addr));
}

__device__ __forceinline__ void mma16816h(float* c, uint32_t a0, uint32_t a1,
                                          uint32_t a2, uint32_t a3,
                                          uint32_t b0, uint32_t b1) {
    asm volatile(
        "mma.sync.aligned.m16n8k16.row.col.f32.f16.f16.f32 "
        "{%0,%1,%2,%3}, {%4,%5,%6,%7}, {%8,%9}, {%0,%1,%2,%3};"
        : "+f"(c[0]), "+f"(c[1]), "+f"(c[2]), "+f"(c[3])
        : "r"(a0), "r"(a1), "r"(a2), "r"(a3), "r"(b0), "r"(b1));
}

#define CP_ASYNC16(dst, src) \
    asm volatile("cp.async.cg.shared.global [%0], [%1], 16;" :: "r"(dst), "l"(src) : "memory")
#define CP_COMMIT() asm volatile("cp.async.commit_group;" ::: "memory")
#define CP_WAIT0()  asm volatile("cp.async.wait_group 0;" ::: "memory")

// ---------------------------------------------------------------------------
// fp32 -> fp16 convert with scale (4 elems/thread)
// ---------------------------------------------------------------------------
__global__ void __launch_bounds__(256) f2h(const float* __restrict__ src,
                                           __half* __restrict__ dst, float scale)
{
    int idx = (blockIdx.x * 256 + threadIdx.x) * 4;
    float4 v = *(const float4*)&src[idx];
    *(__half2*)&dst[idx]     = __floats2half2_rn(v.x * scale, v.y * scale);
    *(__half2*)&dst[idx + 2] = __floats2half2_rn(v.z * scale, v.w * scale);
}

// ---------------------------------------------------------------------------
// fp16 HMMA GEMM: C[4096,1024] = A[4096,1024] @ B[1024,1024]^T
// mma.sync.m16n8k16 fp16->fp32, 128x128 tile, BK=32, 3-stage cp.async,
// padded smem stride 40 halves. F32OUT selects fp32 vs fp16 C.
// ---------------------------------------------------------------------------
#define GS      3
#define BK      32
#define GKIT    (KD / BK)          // 32
#define STRIDE  40
#define TILE_HALVES (128 * STRIDE)
#define STAGE_HALVES (2 * TILE_HALVES)
#define GEMM_SMEM (GS * STAGE_HALVES * 2)   // 61440 B

__device__ __forceinline__ void gemm_fill_stage(
    uint32_t sm_base, int stage, int iter, int tid, int m0, int n0,
    const __half* __restrict__ Ag, const __half* __restrict__ Bg)
{
    const int k0 = iter * BK;
    const uint32_t stage_base = sm_base + stage * (STAGE_HALVES * 2);
    #pragma unroll
    for (int t = 0; t < 2; t++) {
        int c   = tid + t * 256;
        int row = c >> 2;
        int kc  = (c & 3) * 8;
        const __half* srcA = &Ag[(size_t)(m0 + row) * KD + k0 + kc];
        const __half* srcB = &Bg[(size_t)(n0 + row) * KD + k0 + kc];
        uint32_t dstA = stage_base + (row * STRIDE + kc) * 2;
        uint32_t dstB = dstA + TILE_HALVES * 2;
        CP_ASYNC16(dstA, srcA);
        CP_ASYNC16(dstB, srcB);
    }
    CP_COMMIT();
}

template<bool F32OUT>
__global__ void __launch_bounds__(256, 1) gemm_h(const __half* __restrict__ Ag,
                                                 const __half* __restrict__ Bg,
                                                 void* __restrict__ Cv)
{
    extern __shared__ char smem[];
    const uint32_t sm_base = smem_to_u32(smem);
    const int tid  = threadIdx.x;
    const int wid  = tid >> 5;
    const int lane = tid & 31;
    const int m0 = blockIdx.y * 128;
    const int n0 = blockIdx.x * 128;

    const int wm = (wid >> 2) * 64;
    const int wn = (wid & 3) * 32;

    const int q = lane >> 3;
    const int r = lane & 7;

    float acc[4][4][4];
    #pragma unroll
    for (int mi = 0; mi < 4; mi++)
        #pragma unroll
        for (int ni = 0; ni < 4; ni++)
            #pragma unroll
            for (int e = 0; e < 4; e++) acc[mi][ni][e] = 0.0f;

    #pragma unroll
    for (int s = 0; s < GS - 1; s++)
        gemm_fill_stage(sm_base, s, s, tid, m0, n0, Ag, Bg);

    for (int i = 0; i < GKIT; i++) {
        asm volatile("cp.async.wait_group %0;" :: "n"(GS - 2) : "memory");
        __syncthreads();

        const int j = i + GS - 1;
        if (j < GKIT)
            gemm_fill_stage(sm_base, j % GS, j, tid, m0, n0, Ag, Bg);

        const uint32_t stage_base = sm_base + (i % GS) * (STAGE_HALVES * 2);
        const uint32_t bbase = stage_base + TILE_HALVES * 2;

        #pragma unroll
        for (int ks = 0; ks < 2; ks++) {
            const int kh = ks * 16;
            uint32_t af[4][4];
            #pragma unroll
            for (int mi = 0; mi < 4; mi++) {
                int arow = wm + mi * 16 + (q & 1) * 8 + r;
                int acol = kh + (q >> 1) * 8;
                ldsm_x4(af[mi][0], af[mi][1], af[mi][2], af[mi][3],
                        stage_base + (arow * STRIDE + acol) * 2);
            }
            uint32_t bf[4][2];
            #pragma unroll
            for (int p = 0; p < 2; p++) {
                int brow = wn + p * 16 + (q >> 1) * 8 + r;
                int bcol = kh + (q & 1) * 8;
                uint32_t b0, b1, b2, b3;
                ldsm_x4(b0, b1, b2, b3, bbase + (brow * STRIDE + bcol) * 2);
                bf[p * 2 + 0][0] = b0; bf[p * 2 + 0][1] = b1;
                bf[p * 2 + 1][0] = b2; bf[p * 2 + 1][1] = b3;
            }
            #pragma unroll
            for (int mi = 0; mi < 4; mi++)
                #pragma unroll
                for (int ni = 0; ni < 4; ni++)
                    mma16816h(acc[mi][ni], af[mi][0], af[mi][1], af[mi][2], af[mi][3],
                              bf[ni][0], bf[ni][1]);
        }
        __syncthreads();
    }

    const int gp = lane >> 2;
    const int t4 = lane & 3;
    #pragma unroll
    for (int mi = 0; mi < 4; mi++) {
        int row0 = m0 + wm + mi * 16 + gp;
        #pragma unroll
        for (int ni = 0; ni < 4; ni++) {
            int col = n0 + wn + ni * 8 + t4 * 2;
            if (F32OUT) {
                float* C = (float*)Cv;
                *(float2*)&C[(size_t)row0 * 1024 + col] =
                    make_float2(acc[mi][ni][0], acc[mi][ni][1]);
                *(float2*)&C[(size_t)(row0 + 8) * 1024 + col] =
                    make_float2(acc[mi][ni][2], acc[mi][ni][3]);
            } else {
                __half* C = (__half*)Cv;
                *(__half2*)&C[(size_t)row0 * 1024 + col] =
                    __floats2half2_rn(acc[mi][ni][0], acc[mi][ni][1]);
                *(__half2*)&C[(size_t)(row0 + 8) * 1024 + col] =
                    __floats2half2_rn(acc[mi][ni][2], acc[mi][ni][3]);
            }
        }
    }
}

// ---------------------------------------------------------------------------
// Tensor-core flash attention (fp16 operands, fp32 accum, online softmax).
// Block = 64 q-rows of one (b,h); 4 warps. Q pre-scaled via wq conversion.
// Writes ctx as fp16 to g_c16.
// ---------------------------------------------------------------------------
#define ASTR   72
#define ATILE_B (64 * ASTR * 2)
#define AQOFF  0
#define APOFF  (ATILE_B)
#define AKOFF  (2 * ATILE_B)
#define AVOFF  (4 * ATILE_B)
#define ATTN_SMEM (6 * ATILE_B)          // 55296
#define ABN   (-1e30f)

__device__ __forceinline__ void attn_prefetch(uint32_t smK, uint32_t smV,
                                              const __half* Kg, const __half* Vg,
                                              int tid)
{
    #pragma unroll
    for (int c = tid; c < 512; c += 128) {
        int row = c >> 3;
        int ch  = c & 7;
        uint32_t off = row * (ASTR * 2) + ch * 16;
        CP_ASYNC16(smK + off, Kg + (size_t)row * DIMM + ch * 8);
        CP_ASYNC16(smV + off, Vg + (size_t)row * DIMM + ch * 8);
    }
}

__global__ void __launch_bounds__(128) attn_mma()
{
    extern __shared__ char smem[];
    const uint32_t sm = smem_to_u32(smem);
    const int tid  = threadIdx.x;
    const int w    = tid >> 5;
    const int lane = tid & 31;
    const int gp   = lane >> 2;
    const int t4   = lane & 3;
    const int qt = gridDim.x - 1 - blockIdx.x;
    const int h  = blockIdx.y;
    const int b  = blockIdx.z;

    const __half* Qg = g_q16 + (size_t)(b * SEQ + qt * 64) * DIMM + h * HD;
    const __half* Kg = g_k16 + (size_t)(b * SEQ) * DIMM + h * HD;
    const __half* Vg = g_v16 + (size_t)(b * SEQ) * DIMM + h * HD;

    #pragma unroll
    for (int c = tid; c < 512; c += 128) {
        int row = c >> 3, ch = c & 7;
        CP_ASYNC16(sm + AQOFF + row * (ASTR * 2) + ch * 16,
                   Qg + (size_t)row * DIMM + ch * 8);
    }
    CP_COMMIT();
    attn_prefetch(sm + AKOFF, sm + AVOFF, Kg, Vg, tid);
    CP_COMMIT();
    CP_WAIT0();
    __syncthreads();

    uint32_t aQ[4][4];
    #pragma unroll
    for (int ks = 0; ks < 4; ks++)
        ldsm_x4(aQ[ks][0], aQ[ks][1], aQ[ks][2], aQ[ks][3],
                sm + AQOFF + ((w * 16 + (lane & 15)) * ASTR
                              + ks * 16 + (lane >> 4) * 8) * 2);

    float oacc[8][4];
    #pragma unroll
    for (int nf = 0; nf < 8; nf++)
        #pragma unroll
        for (int e = 0; e < 4; e++) oacc[nf][e] = 0.0f;
    float m0 = ABN, m1 = ABN, l0 = 0.0f, l1 = 0.0f;

    for (int t = 0; t <= qt; t++) {
        const uint32_t bufK = sm + AKOFF + (t & 1) * ATILE_B;
        const uint32_t bufV = sm + AVOFF + (t & 1) * ATILE_B;

        if (t > 0) { CP_WAIT0(); __syncthreads(); }
        if (t < qt) {
            attn_prefetch(sm + AKOFF + ((t + 1) & 1) * ATILE_B,
                          sm + AVOFF + ((t + 1) & 1) * ATILE_B,
                          Kg + (size_t)(t + 1) * 64 * DIMM,
                          Vg + (size_t)(t + 1) * 64 * DIMM, tid);
            CP_COMMIT();
        }

        float sacc[8][4];
        #pragma unroll
        for (int nf = 0; nf < 8; nf++)
            #pragma unroll
            for (int e = 0; e < 4; e++) sacc[nf][e] = 0.0f;

        #pragma unroll
        for (int ks = 0; ks < 4; ks++) {
            #pragma unroll
            for (int p = 0; p < 4; p++) {
                uint32_t b0, b1, b2, b3;
                int brow = p * 16 + (lane >> 4) * 8 + (lane & 7);
                int bcol = ks * 16 + ((lane >> 3) & 1) * 8;
                ldsm_x4(b0, b1, b2, b3, bufK + (brow * ASTR + bcol) * 2);
                mma16816h(sacc[2 * p],     aQ[ks][0], aQ[ks][1], aQ[ks][2], aQ[ks][3], b0, b1);
                mma16816h(sacc[2 * p + 1], aQ[ks][0], aQ[ks][1], aQ[ks][2], aQ[ks][3], b2, b3);
            }
        }

        if (t == qt) {
            const int q0 = w * 16 + gp;
            const int q1 = q0 + 8;
            #pragma unroll
            for (int nf = 0; nf < 8; nf++) {
                int c = nf * 8 + t4 * 2;
                if (c     > q0) sacc[nf][0] = ABN;
                if (c + 1 > q0) sacc[nf][1] = ABN;
                if (c     > q1) sacc[nf][2] = ABN;
                if (c + 1 > q1) sacc[nf][3] = ABN;
            }
        }

        float mx0 = ABN, mx1 = ABN;
        #pragma unroll
        for (int nf = 0; nf < 8; nf++) {
            mx0 = fmaxf(mx0, fmaxf(sacc[nf][0], sacc[nf][1]));
            mx1 = fmaxf(mx1, fmaxf(sacc[nf][2], sacc[nf][3]));
        }
        mx0 = fmaxf(mx0, __shfl_xor_sync(0xFFFFFFFF, mx0, 1));
        mx0 = fmaxf(mx0, __shfl_xor_sync(0xFFFFFFFF, mx0, 2));
        mx1 = fmaxf(mx1, __shfl_xor_sync(0xFFFFFFFF, mx1, 1));
        mx1 = fmaxf(mx1, __shfl_xor_sync(0xFFFFFFFF, mx1, 2));

        const float mn0 = fmaxf(m0, mx0);
        const float mn1 = fmaxf(m1, mx1);
        const float cr0 = fast_exp2(m0 - mn0);
        const float cr1 = fast_exp2(m1 - mn1);
        l0 *= cr0;  l1 *= cr1;
        m0 = mn0;   m1 = mn1;

        char* prow0 = smem + APOFF + ((w * 16 + gp) * ASTR + t4 * 2) * 2;
        char* prow1 = prow0 + 8 * ASTR * 2;
        #pragma unroll
        for (int nf = 0; nf < 8; nf++) {
            float p00 = fast_exp2(sacc[nf][0] - mn0);
            float p01 = fast_exp2(sacc[nf][1] - mn0);
            float p10 = fast_exp2(sacc[nf][2] - mn1);
            float p11 = fast_exp2(sacc[nf][3] - mn1);
            l0 += p00 + p01;
            l1 += p10 + p11;
            oacc[nf][0] *= cr0; oacc[nf][1] *= cr0;
            oacc[nf][2] *= cr1; oacc[nf][3] *= cr1;
            *(__half2*)(prow0 + nf * 16) = __floats2half2_rn(p00, p01);
            *(__half2*)(prow1 + nf * 16) = __floats2half2_rn(p10, p11);
        }
        __syncwarp();

        #pragma unroll
        for (int ks = 0; ks < 4; ks++) {
            uint32_t a0, a1, a2, a3;
            ldsm_x4(a0, a1, a2, a3,
                    sm + APOFF + ((w * 16 + (lane & 15)) * ASTR
                                  + ks * 16 + (lane >> 4) * 8) * 2);
            #pragma unroll
            for (int p = 0; p < 4; p++) {
                uint32_t b0, b1, b2, b3;
                int vrow = ks * 16 + (lane & 15);
                int vcol = p * 16 + (lane >> 4) * 8;
                ldsm_x4_t(b0, b1, b2, b3, bufV + (vrow * ASTR + vcol) * 2);
                mma16816h(oacc[2 * p],     a0, a1, a2, a3, b0, b1);
                mma16816h(oacc[2 * p + 1], a0, a1, a2, a3, b2, b3);
            }
        }
    }

    l0 += __shfl_xor_sync(0xFFFFFFFF, l0, 1);
    l0 += __shfl_xor_sync(0xFFFFFFFF, l0, 2);
    l1 += __shfl_xor_sync(0xFFFFFFFF, l1, 1);
    l1 += __shfl_xor_sync(0xFFFFFFFF, l1, 2);
    const float inv0 = 1.0f / l0;
    const float inv1 = 1.0f / l1;

    const int qg = qt * 64 + w * 16 + gp;
    __half* orow = g_c16 + (size_t)(b * SEQ + qg) * DIMM + h * HD;
    #pragma unroll
    for (int nf = 0; nf < 8; nf++) {
        int col = nf * 8 + t4 * 2;
        *(__half2*)(orow + col) =
            __floats2half2_rn(oacc[nf][0] * inv0, oacc[nf][1] * inv0);
        *(__half2*)(orow + 8 * DIMM + col) =
            __floats2half2_rn(oacc[nf][2] * inv1, oacc[nf][3] * inv1);
    }
}

// ---------------------------------------------------------------------------

extern "C" void kernel_launch(void* const* d_in, const int* in_sizes, int n_in,
                              void* d_out, int out_size)
{
    const float* x  = (const float*)d_in[0];
    const float* wq = (const float*)d_in[1];
    const float* wk = (const float*)d_in[2];
    const float* wv = (const float*)d_in[3];
    const float* wo = (const float*)d_in[4];
    float* out = (float*)d_out;

    __half *x16, *q16, *k16, *v16, *c16, *wq16, *wk16, *wv16, *wo16;
    cudaGetSymbolAddress((void**)&x16,  g_x16);
    cudaGetSymbolAddress((void**)&q16,  g_q16);
    cudaGetSymbolAddress((void**)&k16,  g_k16);
    cudaGetSymbolAddress((void**)&v16,  g_v16);
    cudaGetSymbolAddress((void**)&c16,  g_c16);
    cudaGetSymbolAddress((void**)&wq16, g_wq16);
    cudaGetSymbolAddress((void**)&wk16, g_wk16);
    cudaGetSymbolAddress((void**)&wv16, g_wv16);
    cudaGetSymbolAddress((void**)&wo16, g_wo16);

    cudaFuncSetAttribute(gemm_h<false>, cudaFuncAttributeMaxDynamicSharedMemorySize, GEMM_SMEM);
    cudaFuncSetAttribute(gemm_h<true>,  cudaFuncAttributeMaxDynamicSharedMemorySize, GEMM_SMEM);
    cudaFuncSetAttribute(attn_mma, cudaFuncAttributeMaxDynamicSharedMemorySize, ATTN_SMEM);

    const float SC = 0.18033688011112042f;   // 0.125 * log2(e), folded into wq

    f2h<<<(MTOT*DIMM)/(256*4), 256>>>(x,  x16,  1.0f);
    f2h<<<(DIMM*DIMM)/(256*4), 256>>>(wq, wq16, SC);
    f2h<<<(DIMM*DIMM)/(256*4), 256>>>(wk, wk16, 1.0f);
    f2h<<<(DIMM*DIMM)/(256*4), 256>>>(wv, wv16, 1.0f);
    f2h<<<(DIMM*DIMM)/(256*4), 256>>>(wo, wo16, 1.0f);

    dim3 ggrid(1024 / 128, MTOT / 128);   // (8, 32)
    gemm_h<false><<<ggrid, 256, GEMM_SMEM>>>(x16, wq16, q16);
    gemm_h<false><<<ggrid, 256, GEMM_SMEM>>>(x16, wk16, k16);
    gemm_h<false><<<ggrid, 256, GEMM_SMEM>>>(x16, wv16, v16);

    dim3 agrid(SEQ / 64, NH, BATCHN);     // (32, 16, 2)
    attn_mma<<<agrid, 128, ATTN_SMEM>>>();

    gemm_h<true><<<ggrid, 256, GEMM_SMEM>>>(c16, wo16, out);
}

// round 6
// speedup vs baseline: 7.5224x; 1.0933x over previous
#include <cuda_runtime.h>
#include <cuda_fp16.h>
#include <cstdint>
#include <math.h>

#define DIN   1024
#define DIMM  1024
#define NH    16
#define HD    64
#define SEQ   2048
#define BATCHN 2
#define MTOT  (BATCHN*SEQ)   // 4096
#define KD    1024

// ---------------------------------------------------------------------------
// Scratch (allocation-free rule: __device__ globals)
// ---------------------------------------------------------------------------
__device__ __align__(16) __half g_x16[MTOT*DIMM];
__device__ __align__(16) __half g_q16[MTOT*DIMM];
__device__ __align__(16) __half g_k16[MTOT*DIMM];
__device__ __align__(16) __half g_v16[MTOT*DIMM];
__device__ __align__(16) __half g_c16[MTOT*DIMM];
__device__ __align__(16) __half g_wq16[DIMM*DIMM];
__device__ __align__(16) __half g_wk16[DIMM*DIMM];
__device__ __align__(16) __half g_wv16[DIMM*DIMM];
__device__ __align__(16) __half g_wo16[DIMM*DIMM];

__device__ __forceinline__ uint32_t smem_to_u32(const void* smem_ptr) {
    uint32_t addr;
    asm("{ .reg .u64 tmp; cvta.to.shared.u64 tmp, %1; cvt.u32.u64 %0, tmp; }"
        : "=r"(addr) : "l"(smem_ptr));
    return addr;
}

__device__ __forceinline__ float fast_exp2(float x) {
    float y;
    asm("ex2.approx.ftz.f32 %0, %1;" : "=f"(y) : "f"(x));
    return y;
}

__device__ __forceinline__ void ldsm_x4(uint32_t& r0, uint32_t& r1,
                                        uint32_t& r2, uint32_t& r3, uint32_t addr) {
    asm volatile("ldmatrix.sync.aligned.m8n8.x4.shared.b16 {%0,%1,%2,%3}, [%4];"
        : "=r"(r0), "=r"(r1), "=r"(r2), "=r"(r3) : "r"(addr));
}

__device__ __forceinline__ void ldsm_x4_t(uint32_t& r0, uint32_t& r1,
                                          uint32_t& r2, uint32_t& r3, uint32_t addr) {
    asm volatile("ldmatrix.sync.aligned.m8n8.x4.trans.shared.b16 {%0,%1,%2,%3}, [%4];"
        : "=r"(r0), "=r"(r1), "=r"(r2), "=r"(r3) : "r"(addr));
}

__device__ __forceinline__ void mma16816h(float* c, uint32_t a0, uint32_t a1,
                                          uint32_t a2, uint32_t a3,
                                          uint32_t b0, uint32_t b1) {
    asm volatile(
        "mma.sync.aligned.m16n8k16.row.col.f32.f16.f16.f32 "
        "{%0,%1,%2,%3}, {%4,%5,%6,%7}, {%8,%9}, {%0,%1,%2,%3};"
        : "+f"(c[0]), "+f"(c[1]), "+f"(c[2]), "+f"(c[3])
        : "r"(a0), "r"(a1), "r"(a2), "r"(a3), "r"(b0), "r"(b1));
}

#define CP_ASYNC16(dst, src) \
    asm volatile("cp.async.cg.shared.global [%0], [%1], 16;" :: "r"(dst), "l"(src) : "memory")
#define CP_COMMIT() asm volatile("cp.async.commit_group;" ::: "memory")
#define CP_WAIT0()  asm volatile("cp.async.wait_group 0;" ::: "memory")

// ---------------------------------------------------------------------------
// fp32 -> fp16 converts
// ---------------------------------------------------------------------------
__global__ void __launch_bounds__(256) f2h(const float* __restrict__ src,
                                           __half* __restrict__ dst, float scale)
{
    int idx = (blockIdx.x * 256 + threadIdx.x) * 4;
    float4 v = *(const float4*)&src[idx];
    *(__half2*)&dst[idx]     = __floats2half2_rn(v.x * scale, v.y * scale);
    *(__half2*)&dst[idx + 2] = __floats2half2_rn(v.z * scale, v.w * scale);
}

// all 4 weight matrices in one launch; wq gets the attention scale folded in
__global__ void __launch_bounds__(256) wcvt(const float* __restrict__ wq,
                                            const float* __restrict__ wk,
                                            const float* __restrict__ wv,
                                            const float* __restrict__ wo)
{
    const float SC = 0.18033688011112042f;   // 0.125 * log2(e)
    int mat = blockIdx.x >> 10;              // 1024 blocks per matrix
    int idx = ((blockIdx.x & 1023) * 256 + threadIdx.x) * 4;
    const float* src; __half* dst; float s = 1.0f;
    switch (mat) {
        case 0: src = wq; dst = g_wq16; s = SC; break;
        case 1: src = wk; dst = g_wk16; break;
        case 2: src = wv; dst = g_wv16; break;
        default: src = wo; dst = g_wo16; break;
    }
    float4 v = *(const float4*)&src[idx];
    *(__half2*)&dst[idx]     = __floats2half2_rn(v.x * s, v.y * s);
    *(__half2*)&dst[idx + 2] = __floats2half2_rn(v.z * s, v.w * s);
}

// ---------------------------------------------------------------------------
// fp16 HMMA GEMM: 128x256 CTA tile, 64x64 warp tile (8 warps), BK=32,
// 3-stage cp.async. Grid.x selects among up to 3 B/C matrices (QKV fused).
// ---------------------------------------------------------------------------
#define GS       3
#define BK       32
#define GKIT     (KD / BK)            // 32
#define STRIDE   40                   // halves per row (32 + 8 pad)
#define A_HALVES (128 * STRIDE)       // 5120
#define B_HALVES (256 * STRIDE)       // 10240
#define STAGE_HALVES (A_HALVES + B_HALVES)
#define GEMM_SMEM (GS * STAGE_HALVES * 2)    // 92160 B

__device__ __forceinline__ void gemm_fill_stage(
    uint32_t sm_base, int stage, int iter, int tid, int m0, int n0,
    const __half* __restrict__ Ag, const __half* __restrict__ Bg)
{
    const int k0 = iter * BK;
    const uint32_t stage_base = sm_base + stage * (STAGE_HALVES * 2);
    #pragma unroll
    for (int t = 0; t < 6; t++) {
        int c = tid + t * 256;               // 0..1535
        if (c < 512) {                       // A: 128 rows x 4 chunks
            int row = c >> 2, kc = (c & 3) * 8;
            CP_ASYNC16(stage_base + (row * STRIDE + kc) * 2,
                       &Ag[(size_t)(m0 + row) * KD + k0 + kc]);
        } else {                             // B: 256 rows x 4 chunks
            int cb = c - 512;
            int row = cb >> 2, kc = (cb & 3) * 8;
            CP_ASYNC16(stage_base + A_HALVES * 2 + (row * STRIDE + kc) * 2,
                       &Bg[(size_t)(n0 + row) * KD + k0 + kc]);
        }
    }
    CP_COMMIT();
}

template<bool F32OUT>
__global__ void __launch_bounds__(256, 1) gemm_big(
    const __half* __restrict__ Ag,
    const __half* __restrict__ B0, const __half* __restrict__ B1,
    const __half* __restrict__ B2,
    void* __restrict__ C0, void* __restrict__ C1, void* __restrict__ C2,
    int tilesPerMat)
{
    extern __shared__ char smem[];
    const uint32_t sm_base = smem_to_u32(smem);
    const int tid  = threadIdx.x;
    const int wid  = tid >> 5;
    const int lane = tid & 31;
    const int m0  = blockIdx.y * 128;
    const int sel = blockIdx.x / tilesPerMat;
    const int n0  = (blockIdx.x % tilesPerMat) * 256;

    const __half* Bg = (sel == 0) ? B0 : (sel == 1) ? B1 : B2;
    void* Cv = (sel == 0) ? C0 : (sel == 1) ? C1 : C2;

    const int wm = (wid >> 2) * 64;    // 0 / 64
    const int wn = (wid & 3) * 64;     // 0..192

    const int q = lane >> 3;
    const int r = lane & 7;

    float acc[4][8][4];
    #pragma unroll
    for (int mi = 0; mi < 4; mi++)
        #pragma unroll
        for (int nf = 0; nf < 8; nf++)
            #pragma unroll
            for (int e = 0; e < 4; e++) acc[mi][nf][e] = 0.0f;

    #pragma unroll
    for (int s = 0; s < GS - 1; s++)
        gemm_fill_stage(sm_base, s, s, tid, m0, n0, Ag, Bg);

    for (int i = 0; i < GKIT; i++) {
        asm volatile("cp.async.wait_group %0;" :: "n"(GS - 2) : "memory");
        __syncthreads();

        const int j = i + GS - 1;
        if (j < GKIT)
            gemm_fill_stage(sm_base, j % GS, j, tid, m0, n0, Ag, Bg);

        const uint32_t abase = sm_base + (i % GS) * (STAGE_HALVES * 2);
        const uint32_t bbase = abase + A_HALVES * 2;

        #pragma unroll
        for (int ks = 0; ks < 2; ks++) {
            const int kh = ks * 16;
            uint32_t af[4][4];
            #pragma unroll
            for (int mi = 0; mi < 4; mi++) {
                int arow = wm + mi * 16 + (lane & 15);
                int acol = kh + (lane >> 4) * 8;
                ldsm_x4(af[mi][0], af[mi][1], af[mi][2], af[mi][3],
                        abase + (arow * STRIDE + acol) * 2);
            }
            uint32_t bf[8][2];
            #pragma unroll
            for (int p = 0; p < 4; p++) {
                int brow = wn + p * 16 + (q >> 1) * 8 + r;
                int bcol = kh + (q & 1) * 8;
                uint32_t b0, b1, b2, b3;
                ldsm_x4(b0, b1, b2, b3, bbase + (brow * STRIDE + bcol) * 2);
                bf[p * 2 + 0][0] = b0; bf[p * 2 + 0][1] = b1;
                bf[p * 2 + 1][0] = b2; bf[p * 2 + 1][1] = b3;
            }
            #pragma unroll
            for (int mi = 0; mi < 4; mi++)
                #pragma unroll
                for (int nf = 0; nf < 8; nf++)
                    mma16816h(acc[mi][nf], af[mi][0], af[mi][1], af[mi][2], af[mi][3],
                              bf[nf][0], bf[nf][1]);
        }
        __syncthreads();
    }

    const int gp = lane >> 2;
    const int t4 = lane & 3;
    #pragma unroll
    for (int mi = 0; mi < 4; mi++) {
        int row0 = m0 + wm + mi * 16 + gp;
        #pragma unroll
        for (int nf = 0; nf < 8; nf++) {
            int col = n0 + wn + nf * 8 + t4 * 2;
            if (F32OUT) {
                float* C = (float*)Cv;
                *(float2*)&C[(size_t)row0 * 1024 + col] =
                    make_float2(acc[mi][nf][0], acc[mi][nf][1]);
                *(float2*)&C[(size_t)(row0 + 8) * 1024 + col] =
                    make_float2(acc[mi][nf][2], acc[mi][nf][3]);
            } else {
                __half* C = (__half*)Cv;
                *(__half2*)&C[(size_t)row0 * 1024 + col] =
                    __floats2half2_rn(acc[mi][nf][0], acc[mi][nf][1]);
                *(__half2*)&C[(size_t)(row0 + 8) * 1024 + col] =
                    __floats2half2_rn(acc[mi][nf][2], acc[mi][nf][3]);
            }
        }
    }
}

// ---------------------------------------------------------------------------
// Tensor-core flash attention (fp16 operands, fp32 accum, online softmax).
// Unchanged from R5.
// ---------------------------------------------------------------------------
#define ASTR   72
#define ATILE_B (64 * ASTR * 2)
#define AQOFF  0
#define APOFF  (ATILE_B)
#define AKOFF  (2 * ATILE_B)
#define AVOFF  (4 * ATILE_B)
#define ATTN_SMEM (6 * ATILE_B)          // 55296
#define ABN   (-1e30f)

__device__ __forceinline__ void attn_prefetch(uint32_t smK, uint32_t smV,
                                              const __half* Kg, const __half* Vg,
                                              int tid)
{
    #pragma unroll
    for (int c = tid; c < 512; c += 128) {
        int row = c >> 3;
        int ch  = c & 7;
        uint32_t off = row * (ASTR * 2) + ch * 16;
        CP_ASYNC16(smK + off, Kg + (size_t)row * DIMM + ch * 8);
        CP_ASYNC16(smV + off, Vg + (size_t)row * DIMM + ch * 8);
    }
}

__global__ void __launch_bounds__(128) attn_mma()
{
    extern __shared__ char smem[];
    const uint32_t sm = smem_to_u32(smem);
    const int tid  = threadIdx.x;
    const int w    = tid >> 5;
    const int lane = tid & 31;
    const int gp   = lane >> 2;
    const int t4   = lane & 3;
    const int qt = gridDim.x - 1 - blockIdx.x;
    const int h  = blockIdx.y;
    const int b  = blockIdx.z;

    const __half* Qg = g_q16 + (size_t)(b * SEQ + qt * 64) * DIMM + h * HD;
    const __half* Kg = g_k16 + (size_t)(b * SEQ) * DIMM + h * HD;
    const __half* Vg = g_v16 + (size_t)(b * SEQ) * DIMM + h * HD;

    #pragma unroll
    for (int c = tid; c < 512; c += 128) {
        int row = c >> 3, ch = c & 7;
        CP_ASYNC16(sm + AQOFF + row * (ASTR * 2) + ch * 16,
                   Qg + (size_t)row * DIMM + ch * 8);
    }
    CP_COMMIT();
    attn_prefetch(sm + AKOFF, sm + AVOFF, Kg, Vg, tid);
    CP_COMMIT();
    CP_WAIT0();
    __syncthreads();

    uint32_t aQ[4][4];
    #pragma unroll
    for (int ks = 0; ks < 4; ks++)
        ldsm_x4(aQ[ks][0], aQ[ks][1], aQ[ks][2], aQ[ks][3],
                sm + AQOFF + ((w * 16 + (lane & 15)) * ASTR
                              + ks * 16 + (lane >> 4) * 8) * 2);

    float oacc[8][4];
    #pragma unroll
    for (int nf = 0; nf < 8; nf++)
        #pragma unroll
        for (int e = 0; e < 4; e++) oacc[nf][e] = 0.0f;
    float m0 = ABN, m1 = ABN, l0 = 0.0f, l1 = 0.0f;

    for (int t = 0; t <= qt; t++) {
        const uint32_t bufK = sm + AKOFF + (t & 1) * ATILE_B;
        const uint32_t bufV = sm + AVOFF + (t & 1) * ATILE_B;

        if (t > 0) { CP_WAIT0(); __syncthreads(); }
        if (t < qt) {
            attn_prefetch(sm + AKOFF + ((t + 1) & 1) * ATILE_B,
                          sm + AVOFF + ((t + 1) & 1) * ATILE_B,
                          Kg + (size_t)(t + 1) * 64 * DIMM,
                          Vg + (size_t)(t + 1) * 64 * DIMM, tid);
            CP_COMMIT();
        }

        float sacc[8][4];
        #pragma unroll
        for (int nf = 0; nf < 8; nf++)
            #pragma unroll
            for (int e = 0; e < 4; e++) sacc[nf][e] = 0.0f;

        #pragma unroll
        for (int ks = 0; ks < 4; ks++) {
            #pragma unroll
            for (int p = 0; p < 4; p++) {
                uint32_t b0, b1, b2, b3;
                int brow = p * 16 + (lane >> 4) * 8 + (lane & 7);
                int bcol = ks * 16 + ((lane >> 3) & 1) * 8;
                ldsm_x4(b0, b1, b2, b3, bufK + (brow * ASTR + bcol) * 2);
                mma16816h(sacc[2 * p],     aQ[ks][0], aQ[ks][1], aQ[ks][2], aQ[ks][3], b0, b1);
                mma16816h(sacc[2 * p + 1], aQ[ks][0], aQ[ks][1], aQ[ks][2], aQ[ks][3], b2, b3);
            }
        }

        if (t == qt) {
            const int q0 = w * 16 + gp;
            const int q1 = q0 + 8;
            #pragma unroll
            for (int nf = 0; nf < 8; nf++) {
                int c = nf * 8 + t4 * 2;
                if (c     > q0) sacc[nf][0] = ABN;
                if (c + 1 > q0) sacc[nf][1] = ABN;
                if (c     > q1) sacc[nf][2] = ABN;
                if (c + 1 > q1) sacc[nf][3] = ABN;
            }
        }

        float mx0 = ABN, mx1 = ABN;
        #pragma unroll
        for (int nf = 0; nf < 8; nf++) {
            mx0 = fmaxf(mx0, fmaxf(sacc[nf][0], sacc[nf][1]));
            mx1 = fmaxf(mx1, fmaxf(sacc[nf][2], sacc[nf][3]));
        }
        mx0 = fmaxf(mx0, __shfl_xor_sync(0xFFFFFFFF, mx0, 1));
        mx0 = fmaxf(mx0, __shfl_xor_sync(0xFFFFFFFF, mx0, 2));
        mx1 = fmaxf(mx1, __shfl_xor_sync(0xFFFFFFFF, mx1, 1));
        mx1 = fmaxf(mx1, __shfl_xor_sync(0xFFFFFFFF, mx1, 2));

        const float mn0 = fmaxf(m0, mx0);
        const float mn1 = fmaxf(m1, mx1);
        const float cr0 = fast_exp2(m0 - mn0);
        const float cr1 = fast_exp2(m1 - mn1);
        l0 *= cr0;  l1 *= cr1;
        m0 = mn0;   m1 = mn1;

        char* prow0 = smem + APOFF + ((w * 16 + gp) * ASTR + t4 * 2) * 2;
        char* prow1 = prow0 + 8 * ASTR * 2;
        #pragma unroll
        for (int nf = 0; nf < 8; nf++) {
            float p00 = fast_exp2(sacc[nf][0] - mn0);
            float p01 = fast_exp2(sacc[nf][1] - mn0);
            float p10 = fast_exp2(sacc[nf][2] - mn1);
            float p11 = fast_exp2(sacc[nf][3] - mn1);
            l0 += p00 + p01;
            l1 += p10 + p11;
            oacc[nf][0] *= cr0; oacc[nf][1] *= cr0;
            oacc[nf][2] *= cr1; oacc[nf][3] *= cr1;
            *(__half2*)(prow0 + nf * 16) = __floats2half2_rn(p00, p01);
            *(__half2*)(prow1 + nf * 16) = __floats2half2_rn(p10, p11);
        }
        __syncwarp();

        #pragma unroll
        for (int ks = 0; ks < 4; ks++) {
            uint32_t a0, a1, a2, a3;
            ldsm_x4(a0, a1, a2, a3,
                    sm + APOFF + ((w * 16 + (lane & 15)) * ASTR
                                  + ks * 16 + (lane >> 4) * 8) * 2);
            #pragma unroll
            for (int p = 0; p < 4; p++) {
                uint32_t b0, b1, b2, b3;
                int vrow = ks * 16 + (lane & 15);
                int vcol = p * 16 + (lane >> 4) * 8;
                ldsm_x4_t(b0, b1, b2, b3, bufV + (vrow * ASTR + vcol) * 2);
                mma16816h(oacc[2 * p],     a0, a1, a2, a3, b0, b1);
                mma16816h(oacc[2 * p + 1], a0, a1, a2, a3, b2, b3);
            }
        }
    }

    l0 += __shfl_xor_sync(0xFFFFFFFF, l0, 1);
    l0 += __shfl_xor_sync(0xFFFFFFFF, l0, 2);
    l1 += __shfl_xor_sync(0xFFFFFFFF, l1, 1);
    l1 += __shfl_xor_sync(0xFFFFFFFF, l1, 2);
    const float inv0 = 1.0f / l0;
    const float inv1 = 1.0f / l1;

    const int qg = qt * 64 + w * 16 + gp;
    __half* orow = g_c16 + (size_t)(b * SEQ + qg) * DIMM + h * HD;
    #pragma unroll
    for (int nf = 0; nf < 8; nf++) {
        int col = nf * 8 + t4 * 2;
        *(__half2*)(orow + col) =
            __floats2half2_rn(oacc[nf][0] * inv0, oacc[nf][1] * inv0);
        *(__half2*)(orow + 8 * DIMM + col) =
            __floats2half2_rn(oacc[nf][2] * inv1, oacc[nf][3] * inv1);
    }
}

// ---------------------------------------------------------------------------

extern "C" void kernel_launch(void* const* d_in, const int* in_sizes, int n_in,
                              void* d_out, int out_size)
{
    const float* x  = (const float*)d_in[0];
    const float* wq = (const float*)d_in[1];
    const float* wk = (const float*)d_in[2];
    const float* wv = (const float*)d_in[3];
    const float* wo = (const float*)d_in[4];
    float* out = (float*)d_out;

    __half *x16, *q16, *k16, *v16, *c16, *wq16, *wk16, *wv16, *wo16;
    cudaGetSymbolAddress((void**)&x16,  g_x16);
    cudaGetSymbolAddress((void**)&q16,  g_q16);
    cudaGetSymbolAddress((void**)&k16,  g_k16);
    cudaGetSymbolAddress((void**)&v16,  g_v16);
    cudaGetSymbolAddress((void**)&c16,  g_c16);
    cudaGetSymbolAddress((void**)&wq16, g_wq16);
    cudaGetSymbolAddress((void**)&wk16, g_wk16);
    cudaGetSymbolAddress((void**)&wv16, g_wv16);
    cudaGetSymbolAddress((void**)&wo16, g_wo16);

    cudaFuncSetAttribute(gemm_big<false>, cudaFuncAttributeMaxDynamicSharedMemorySize, GEMM_SMEM);
    cudaFuncSetAttribute(gemm_big<true>,  cudaFuncAttributeMaxDynamicSharedMemorySize, GEMM_SMEM);
    cudaFuncSetAttribute(attn_mma, cudaFuncAttributeMaxDynamicSharedMemorySize, ATTN_SMEM);

    f2h<<<(MTOT*DIMM)/(256*4), 256>>>(x, x16, 1.0f);
    wcvt<<<4 * (DIMM*DIMM)/(256*4), 256>>>(wq, wk, wv, wo);

    // fused QKV: grid.x = 3 mats x 4 n-tiles
    dim3 gq(12, MTOT / 128);
    gemm_big<false><<<gq, 256, GEMM_SMEM>>>(x16, wq16, wk16, wv16,
                                            q16, k16, v16, 4);

    dim3 agrid(SEQ / 64, NH, BATCHN);     // (32, 16, 2)
    attn_mma<<<agrid, 128, ATTN_SMEM>>>();

    dim3 go(4, MTOT / 128);
    gemm_big<true><<<go, 256, GEMM_SMEM>>>(c16, wo16, wo16, wo16,
                                           out, out, out, 4);
}